// round 3
// baseline (speedup 1.0000x reference)
#include <cuda_runtime.h>
#include <cstdint>

// Submanifold sparse conv — warp-per-site, tap-compacted, software-pipelined.
// features [N,32] f32, weight [27,32,32] f32 (k,ci,cout), bias [32] f32,
// nbr_idx [N,27] i32, nbr_mask [N,27] i32, out [N,32] f32.
//
// smem weights transposed to wT[k][cout][ci] with float4 xor swizzle so the
// per-lane (lane=cout) weight read is a conflict-free LDS.128.

#define C 32
#define KTAPS 27
#define WARPS_PER_BLOCK 12
#define THREADS (WARPS_PER_BLOCK * 32)
#define NBLOCKS 296   // 2 per SM on 148 SMs

#define W_FLOATS (KTAPS * C * C)          // 27648
// weights + per-warp double-buffered feature rows
#define SMEM_BYTES (W_FLOATS * 4 + WARPS_PER_BLOCK * 2 * C * 4)

__global__ void __launch_bounds__(THREADS, 2)
subm_conv_kernel(const float* __restrict__ features,
                 const float* __restrict__ weight,
                 const float* __restrict__ bias,
                 const int*   __restrict__ nbr_idx,
                 const int*   __restrict__ nbr_mask,
                 float* __restrict__ out,
                 int n_sites)
{
    extern __shared__ float smem[];
    float* ws = smem;                                  // [27][32][32] transposed+swizzled
    float* sf = smem + W_FLOATS;                       // [WARPS][2][32]

    const int tid  = threadIdx.x;
    const int lane = tid & 31;
    const int wib  = tid >> 5;
    const int swz  = lane & 7;

    // Stage weights transposed: wT[k][cout][ci], float4-group xor swizzle by cout&7.
    // Source read fully coalesced (idx linear, cout = idx&31).
    for (int idx = tid; idx < W_FLOATS; idx += THREADS) {
        const int k    = idx >> 10;           // /1024
        const int r    = idx & 1023;
        const int ci   = r >> 5;
        const int cout = r & 31;
        const float w  = weight[idx];
        const int g    = (ci >> 2) ^ (cout & 7);
        ws[k * 1024 + cout * 32 + (g << 2) + (ci & 3)] = w;
    }
    __syncthreads();

    const float my_bias = bias[lane];
    float* row0 = sf + wib * (2 * C);
    float* row1 = row0 + C;

    const int gwarp  = blockIdx.x * WARPS_PER_BLOCK + wib;
    const int nwarps = gridDim.x * WARPS_PER_BLOCK;

    // prime first site's idx/mask
    int  cidx = 0;
    bool cok  = false;
    if (gwarp < n_sites && lane < KTAPS) {
        cidx = nbr_idx[gwarp * KTAPS + lane];
        cok  = (nbr_mask[gwarp * KTAPS + lane] != 0);
    }

    for (int site = gwarp; site < n_sites; site += nwarps) {
        // prefetch next site's idx/mask early (hides DRAM latency)
        const int nsite = site + nwarps;
        int  nidx = 0;
        bool nok  = false;
        if (nsite < n_sites && lane < KTAPS) {
            nidx = nbr_idx[nsite * KTAPS + lane];
            nok  = (nbr_mask[nsite * KTAPS + lane] != 0);
        }

        unsigned active = __ballot_sync(0xffffffffu, cok);
        float acc = my_bias;

        if (active) {
            // prime first tap's feature element
            int k = __ffs(active) - 1;
            active &= active - 1;
            int nb = __shfl_sync(0xffffffffu, cidx, k);
            float fv = features[nb * C + lane];

            float* bufs[2] = { row0, row1 };
            int buf = 0;
            while (true) {
                // issue next tap's gather before computing current tap
                int   k2  = -1;
                float fv2 = 0.f;
                if (active) {
                    k2 = __ffs(active) - 1;
                    active &= active - 1;
                    const int nb2 = __shfl_sync(0xffffffffu, cidx, k2);
                    fv2 = features[nb2 * C + lane];
                }

                float* row = bufs[buf];
                row[lane] = fv;
                __syncwarp();

                const float* wk = ws + k * 1024 + lane * 32;
                #pragma unroll
                for (int g = 0; g < 8; ++g) {
                    const float4 f = *reinterpret_cast<const float4*>(row + (g << 2));
                    const float4 w = *reinterpret_cast<const float4*>(wk + (((g ^ swz) & 7) << 2));
                    acc += f.x * w.x;
                    acc += f.y * w.y;
                    acc += f.z * w.z;
                    acc += f.w * w.w;
                }

                if (k2 < 0) break;
                k  = k2;
                fv = fv2;
                buf ^= 1;
            }
        }

        out[site * C + lane] = acc;

        cidx = nidx;
        cok  = nok;
    }
}

extern "C" void kernel_launch(void* const* d_in, const int* in_sizes, int n_in,
                              void* d_out, int out_size)
{
    const float* features = (const float*)d_in[0];
    const float* weight   = (const float*)d_in[1];
    const float* bias     = (const float*)d_in[2];
    const int*   nbr_idx  = (const int*)d_in[3];
    const int*   nbr_mask = (const int*)d_in[4];
    float*       out      = (float*)d_out;

    const int n_sites = in_sizes[0] / C;

    static bool attr_set = false;
    if (!attr_set) {
        cudaFuncSetAttribute(subm_conv_kernel,
                             cudaFuncAttributeMaxDynamicSharedMemorySize,
                             SMEM_BYTES);
        attr_set = true;
    }

    subm_conv_kernel<<<NBLOCKS, THREADS, SMEM_BYTES>>>(
        features, weight, bias, nbr_idx, nbr_mask, out, n_sites);
}

// round 4
// speedup vs baseline: 1.3684x; 1.3684x over previous
#include <cuda_runtime.h>
#include <cstdint>

// Submanifold sparse conv — warp-per-site, tap-compacted, reg-pipelined.
// features [N,32] f32, weight [27,32,32] f32 (k,ci,cout), bias [32] f32,
// nbr_idx [N,27] i32, nbr_mask [N,27] i32, out [N,32] f32.

#define C 32
#define KTAPS 27
#define WARPS_PER_BLOCK 16
#define THREADS 512
#define NBLOCKS 296   // 2 per SM on 148 SMs

#define W_FLOATS (KTAPS * C * C)          // 27648
#define SMEM_BYTES (W_FLOATS * 4 + WARPS_PER_BLOCK * C * 4)   // 112.6 KB

__global__ void __launch_bounds__(THREADS, 2)
subm_conv_kernel(const float* __restrict__ features,
                 const float* __restrict__ weight,
                 const float* __restrict__ bias,
                 const int*   __restrict__ nbr_idx,
                 const int*   __restrict__ nbr_mask,
                 float* __restrict__ out,
                 int n_sites)
{
    extern __shared__ float smem[];
    float* ws = smem;                      // [27][32][32] (k, ci, cout) — as in gmem
    float* sf = smem + W_FLOATS;           // [WARPS][32] feature staging rows

    const int tid  = threadIdx.x;
    const int lane = tid & 31;
    const int wib  = tid >> 5;

    // Stage weights (coalesced float4, layout unchanged).
    {
        const float4* wsrc = reinterpret_cast<const float4*>(weight);
        float4* wdst = reinterpret_cast<float4*>(ws);
        for (int i = tid; i < W_FLOATS / 4; i += THREADS)
            wdst[i] = wsrc[i];
    }
    __syncthreads();

    const float my_bias = bias[lane];
    float* row = sf + wib * C;

    const int gwarp  = blockIdx.x * WARPS_PER_BLOCK + wib;
    const int nwarps = gridDim.x * WARPS_PER_BLOCK;

    // prime first site's idx/mask
    int  cidx = 0;
    bool cok  = false;
    if (gwarp < n_sites && lane < KTAPS) {
        cidx = nbr_idx[gwarp * KTAPS + lane];
        cok  = (nbr_mask[gwarp * KTAPS + lane] != 0);
    }

    for (int site = gwarp; site < n_sites; site += nwarps) {
        // prefetch next site's idx/mask (hides header latency)
        const int nsite = site + nwarps;
        int  nidx = 0;
        bool nok  = false;
        if (nsite < n_sites && lane < KTAPS) {
            nidx = nbr_idx[nsite * KTAPS + lane];
            nok  = (nbr_mask[nsite * KTAPS + lane] != 0);
        }

        unsigned active = __ballot_sync(0xffffffffu, cok);
        float acc = my_bias;

        if (active) {
            // prime first tap's gather (in registers)
            int k = __ffs(active) - 1;
            active &= active - 1;
            int nb = __shfl_sync(0xffffffffu, cidx, k);
            float fvA = features[nb * C + lane];

            while (true) {
                // issue next tap's gather before computing current tap
                int   k2  = -1;
                float fvB = 0.f;
                if (active) {
                    k2 = __ffs(active) - 1;
                    active &= active - 1;
                    const int nb2 = __shfl_sync(0xffffffffu, cidx, k2);
                    fvB = features[nb2 * C + lane];
                }

                row[lane] = fvA;
                __syncwarp();

                const float* wk = ws + (k << 10);   // k*1024
                #pragma unroll
                for (int g = 0; g < 8; ++g) {
                    const float4 f = *reinterpret_cast<const float4*>(row + (g << 2));
                    acc += f.x * wk[((g << 2) + 0) * C + lane];
                    acc += f.y * wk[((g << 2) + 1) * C + lane];
                    acc += f.z * wk[((g << 2) + 2) * C + lane];
                    acc += f.w * wk[((g << 2) + 3) * C + lane];
                }
                __syncwarp();   // WAR: row overwritten next iteration

                if (k2 < 0) break;
                k   = k2;
                fvA = fvB;
            }
        }

        out[site * C + lane] = acc;

        cidx = nidx;
        cok  = nok;
    }
}

extern "C" void kernel_launch(void* const* d_in, const int* in_sizes, int n_in,
                              void* d_out, int out_size)
{
    const float* features = (const float*)d_in[0];
    const float* weight   = (const float*)d_in[1];
    const float* bias     = (const float*)d_in[2];
    const int*   nbr_idx  = (const int*)d_in[3];
    const int*   nbr_mask = (const int*)d_in[4];
    float*       out      = (float*)d_out;

    const int n_sites = in_sizes[0] / C;

    static bool attr_set = false;
    if (!attr_set) {
        cudaFuncSetAttribute(subm_conv_kernel,
                             cudaFuncAttributeMaxDynamicSharedMemorySize,
                             SMEM_BYTES);
        attr_set = true;
    }

    subm_conv_kernel<<<NBLOCKS, THREADS, SMEM_BYTES>>>(
        features, weight, bias, nbr_idx, nbr_mask, out, n_sites);
}

// round 5
// speedup vs baseline: 1.4513x; 1.0606x over previous
#include <cuda_runtime.h>
#include <cstdint>

// Submanifold sparse conv, split formulation:
//  Kernel 1: center tap (k=13, always active, identity gather) as a dense
//            register-weight GEMM: out = bias + F @ W13.
//  Kernel 2: remaining 26 taps, warp-per-site tap-compacted, smem weights,
//            accumulating into out.
//
// features [N,32] f32, weight [27,32,32] f32 (k,ci,cout), bias [32] f32,
// nbr_idx [N,27] i32, nbr_mask [N,27] i32, out [N,32] f32.

#define C 32
#define KTAPS 27
#define KCENTER 13
#define WARPS_PER_BLOCK 16
#define THREADS 512
#define NBLOCKS 296   // 2 per SM on 148 SMs

#define W_FLOATS (KTAPS * C * C)          // 27648
#define SMEM2_BYTES (W_FLOATS * 4 + WARPS_PER_BLOCK * C * 4)   // 112.6 KB

// ---------------- Kernel 1: center GEMM, register-resident W13 ----------------
__global__ void __launch_bounds__(THREADS, 2)
center_gemm_kernel(const float* __restrict__ features,
                   const float* __restrict__ weight,
                   const float* __restrict__ bias,
                   float* __restrict__ out,
                   int n_sites)
{
    __shared__ float sf[WARPS_PER_BLOCK][C];

    const int tid  = threadIdx.x;
    const int lane = tid & 31;
    const int wib  = tid >> 5;

    // W13[ci][lane] into 32 registers (L2/L1-hot broadcast loads)
    float w[C];
    const float* w13 = weight + KCENTER * C * C;
    #pragma unroll
    for (int ci = 0; ci < C; ++ci)
        w[ci] = w13[ci * C + lane];

    const float my_bias = bias[lane];
    float* row = sf[wib];

    const int gwarp  = blockIdx.x * WARPS_PER_BLOCK + wib;
    const int nwarps = gridDim.x * WARPS_PER_BLOCK;

    // prime first site's feature element
    float fvA = 0.f;
    if (gwarp < n_sites) fvA = features[gwarp * C + lane];

    for (int site = gwarp; site < n_sites; site += nwarps) {
        // prefetch next site's feature element
        const int nsite = site + nwarps;
        float fvB = 0.f;
        if (nsite < n_sites) fvB = features[nsite * C + lane];

        row[lane] = fvA;
        __syncwarp();

        float acc = my_bias;
        #pragma unroll
        for (int g = 0; g < 8; ++g) {
            const float4 f = *reinterpret_cast<const float4*>(row + (g << 2));
            acc += f.x * w[(g << 2) + 0];
            acc += f.y * w[(g << 2) + 1];
            acc += f.z * w[(g << 2) + 2];
            acc += f.w * w[(g << 2) + 3];
        }
        __syncwarp();   // WAR on row

        out[site * C + lane] = acc;
        fvA = fvB;
    }
}

// ---------------- Kernel 2: non-center taps, compacted, out += ----------------
__global__ void __launch_bounds__(THREADS, 2)
offcenter_kernel(const float* __restrict__ features,
                 const float* __restrict__ weight,
                 const int*   __restrict__ nbr_idx,
                 const int*   __restrict__ nbr_mask,
                 float* __restrict__ out,
                 int n_sites)
{
    extern __shared__ float smem[];
    float* ws = smem;                      // [27][32][32] (k, ci, cout)
    float* sf = smem + W_FLOATS;           // [WARPS][32]

    const int tid  = threadIdx.x;
    const int lane = tid & 31;
    const int wib  = tid >> 5;

    // Stage weights (coalesced float4)
    {
        const float4* wsrc = reinterpret_cast<const float4*>(weight);
        float4* wdst = reinterpret_cast<float4*>(ws);
        for (int i = tid; i < W_FLOATS / 4; i += THREADS)
            wdst[i] = wsrc[i];
    }
    __syncthreads();

    float* row = sf + wib * C;

    const int gwarp  = blockIdx.x * WARPS_PER_BLOCK + wib;
    const int nwarps = gridDim.x * WARPS_PER_BLOCK;

    // prime first site's mask
    bool cok = false;
    if (gwarp < n_sites && lane < KTAPS)
        cok = (nbr_mask[gwarp * KTAPS + lane] != 0);

    for (int site = gwarp; site < n_sites; site += nwarps) {
        // prefetch next site's mask
        const int nsite = site + nwarps;
        bool nok = false;
        if (nsite < n_sites && lane < KTAPS)
            nok = (nbr_mask[nsite * KTAPS + lane] != 0);

        unsigned active = __ballot_sync(0xffffffffu, cok) & ~(1u << KCENTER);

        if (active) {
            float acc = 0.f;

            // prime first tap: uniform idx load + gather
            int k = __ffs(active) - 1;
            active &= active - 1;
            int nb = nbr_idx[site * KTAPS + k];         // uniform address
            float fvA = features[nb * C + lane];

            while (true) {
                // issue next tap's gather before computing current tap
                int   k2  = -1;
                float fvB = 0.f;
                if (active) {
                    k2 = __ffs(active) - 1;
                    active &= active - 1;
                    const int nb2 = nbr_idx[site * KTAPS + k2];
                    fvB = features[nb2 * C + lane];
                }

                row[lane] = fvA;
                __syncwarp();

                const float* wk = ws + (k << 10);
                #pragma unroll
                for (int g = 0; g < 8; ++g) {
                    const float4 f = *reinterpret_cast<const float4*>(row + (g << 2));
                    acc += f.x * wk[((g << 2) + 0) * C + lane];
                    acc += f.y * wk[((g << 2) + 1) * C + lane];
                    acc += f.z * wk[((g << 2) + 2) * C + lane];
                    acc += f.w * wk[((g << 2) + 3) * C + lane];
                }
                __syncwarp();   // WAR on row

                if (k2 < 0) break;
                k   = k2;
                fvA = fvB;
            }

            out[site * C + lane] += acc;   // kernel1 already wrote bias+center
        }

        cok = nok;
    }
}

extern "C" void kernel_launch(void* const* d_in, const int* in_sizes, int n_in,
                              void* d_out, int out_size)
{
    const float* features = (const float*)d_in[0];
    const float* weight   = (const float*)d_in[1];
    const float* bias     = (const float*)d_in[2];
    const int*   nbr_idx  = (const int*)d_in[3];
    const int*   nbr_mask = (const int*)d_in[4];
    float*       out      = (float*)d_out;

    const int n_sites = in_sizes[0] / C;

    static bool attr_set = false;
    if (!attr_set) {
        cudaFuncSetAttribute(offcenter_kernel,
                             cudaFuncAttributeMaxDynamicSharedMemorySize,
                             SMEM2_BYTES);
        attr_set = true;
    }

    center_gemm_kernel<<<NBLOCKS, THREADS>>>(features, weight, bias, out, n_sites);
    offcenter_kernel<<<NBLOCKS, THREADS, SMEM2_BYTES>>>(
        features, weight, nbr_idx, nbr_mask, out, n_sites);
}

// round 6
// speedup vs baseline: 1.4582x; 1.0047x over previous
#include <cuda_runtime.h>
#include <cstdint>

// Submanifold sparse conv — compacted per-offset gather-GEMM formulation.
//  zero_kernel    : reset per-k counters
//  compact_kernel : build per-k lists of (site, neighbor) for active off-center taps
//  center_gemm    : out = bias + F @ W[13]   (center tap always active, no gather)
//  taps_kernel    : for each k != 13: out[site] += F[nb] @ W[k], W[k] in registers
//
// features [N,32] f32, weight [27,32,32] f32 (k,ci,cout), bias [32] f32,
// nbr_idx [N,27] i32, nbr_mask [N,27] i32, out [N,32] f32.

#define C 32
#define KTAPS 27
#define KCENTER 13
#define NCAP 131072                     // per-k list capacity (N = 100000)

__device__ int  g_count[KTAPS];
__device__ int2 g_list[KTAPS * NCAP];   // (site, neighbor)

// ---------------------------------------------------------------- zero
__global__ void zero_kernel()
{
    if (threadIdx.x < KTAPS) g_count[threadIdx.x] = 0;
}

// ---------------------------------------------------------------- compact
#define CB_THREADS 256
#define CB_SPT 4                        // sites per thread
#define CB_SITES (CB_THREADS * CB_SPT)  // 1024 sites per block

__global__ void __launch_bounds__(CB_THREADS)
compact_kernel(const int* __restrict__ nbr_idx,
               const int* __restrict__ nbr_mask,
               int n_sites)
{
    __shared__ int scount[KTAPS];
    __shared__ int sbase[KTAPS];

    const int tid = threadIdx.x;
    if (tid < KTAPS) scount[tid] = 0;
    __syncthreads();

    const int base_site = blockIdx.x * CB_SITES;
    unsigned bits[CB_SPT];

    // pass 1: read masks, record active bits, count per k in smem
    #pragma unroll
    for (int s = 0; s < CB_SPT; ++s) {
        const int site = base_site + s * CB_THREADS + tid;
        unsigned b = 0;
        if (site < n_sites) {
            const int* m = nbr_mask + site * KTAPS;
            #pragma unroll
            for (int k = 0; k < KTAPS; ++k)
                if (k != KCENTER && m[k]) b |= (1u << k);
        }
        bits[s] = b;
        unsigned t = b;
        while (t) {
            const int k = __ffs(t) - 1;
            t &= t - 1;
            atomicAdd(&scount[k], 1);
        }
    }
    __syncthreads();

    // reserve global space: one global atomic per k per block
    if (tid < KTAPS) {
        const int c = scount[tid];
        sbase[tid]  = c ? atomicAdd(&g_count[tid], c) : 0;
        scount[tid] = 0;                 // reuse as cursor
    }
    __syncthreads();

    // pass 2: write entries
    #pragma unroll
    for (int s = 0; s < CB_SPT; ++s) {
        const int site = base_site + s * CB_THREADS + tid;
        unsigned t = bits[s];
        while (t) {
            const int k = __ffs(t) - 1;
            t &= t - 1;
            const int pos = sbase[k] + atomicAdd(&scount[k], 1);
            g_list[k * NCAP + pos] = make_int2(site, nbr_idx[site * KTAPS + k]);
        }
    }
}

// ---------------------------------------------------------------- center
#define CG_WARPS 16
#define CG_THREADS 512
#define CG_BLOCKS 296

__global__ void __launch_bounds__(CG_THREADS, 2)
center_gemm_kernel(const float* __restrict__ features,
                   const float* __restrict__ weight,
                   const float* __restrict__ bias,
                   float* __restrict__ out,
                   int n_sites)
{
    __shared__ float sf[CG_WARPS][C];

    const int tid  = threadIdx.x;
    const int lane = tid & 31;
    const int wib  = tid >> 5;

    float w[C];
    const float* w13 = weight + KCENTER * C * C;
    #pragma unroll
    for (int ci = 0; ci < C; ++ci)
        w[ci] = w13[ci * C + lane];

    const float my_bias = bias[lane];
    float* row = sf[wib];

    const int gwarp  = blockIdx.x * CG_WARPS + wib;
    const int nwarps = gridDim.x * CG_WARPS;

    float fvA = 0.f;
    if (gwarp < n_sites) fvA = features[gwarp * C + lane];

    for (int site = gwarp; site < n_sites; site += nwarps) {
        const int nsite = site + nwarps;
        float fvB = 0.f;
        if (nsite < n_sites) fvB = features[nsite * C + lane];

        row[lane] = fvA;
        __syncwarp();

        float a0 = my_bias, a1 = 0.f, a2 = 0.f, a3 = 0.f;
        #pragma unroll
        for (int g = 0; g < 8; ++g) {
            const float4 f = *reinterpret_cast<const float4*>(row + (g << 2));
            a0 += f.x * w[(g << 2) + 0];
            a1 += f.y * w[(g << 2) + 1];
            a2 += f.z * w[(g << 2) + 2];
            a3 += f.w * w[(g << 2) + 3];
        }
        __syncwarp();

        out[site * C + lane] = (a0 + a1) + (a2 + a3);
        fvA = fvB;
    }
}

// ---------------------------------------------------------------- taps
#define PB_WARPS 4
#define PB_THREADS 128
#define PB_BLOCKS_X 48

__global__ void __launch_bounds__(PB_THREADS)
taps_kernel(const float* __restrict__ features,
            const float* __restrict__ weight,
            float* __restrict__ out)
{
    __shared__ float rows[PB_WARPS][C];

    int k = blockIdx.y;
    if (k >= KCENTER) ++k;               // skip center

    const int tid  = threadIdx.x;
    const int lane = tid & 31;
    const int wib  = tid >> 5;

    // W[k][ci][lane] in registers
    float w[C];
    const float* wk = weight + k * C * C;
    #pragma unroll
    for (int ci = 0; ci < C; ++ci)
        w[ci] = wk[ci * C + lane];

    const int cnt    = g_count[k];
    const int stride = gridDim.x * PB_WARPS;
    int e = blockIdx.x * PB_WARPS + wib;
    if (e >= cnt) return;

    const int2* list = g_list + k * NCAP;
    float* row = rows[wib];

    // prime first entry
    int2  ent = list[e];
    float fv  = features[ent.y * C + lane];

    while (true) {
        // prefetch next entry + its feature row
        const int e2 = e + stride;
        const bool has2 = (e2 < cnt);
        int2  ent2 = make_int2(0, 0);
        float fv2  = 0.f;
        if (has2) {
            ent2 = list[e2];
            fv2  = features[ent2.y * C + lane];
        }

        row[lane] = fv;
        __syncwarp();

        float a0 = 0.f, a1 = 0.f, a2 = 0.f, a3 = 0.f;
        #pragma unroll
        for (int g = 0; g < 8; ++g) {
            const float4 f = *reinterpret_cast<const float4*>(row + (g << 2));
            a0 += f.x * w[(g << 2) + 0];
            a1 += f.y * w[(g << 2) + 1];
            a2 += f.z * w[(g << 2) + 2];
            a3 += f.w * w[(g << 2) + 3];
        }
        __syncwarp();

        atomicAdd(&out[ent.x * C + lane], (a0 + a1) + (a2 + a3));

        if (!has2) break;
        e = e2; ent = ent2; fv = fv2;
    }
}

// ---------------------------------------------------------------- launch
extern "C" void kernel_launch(void* const* d_in, const int* in_sizes, int n_in,
                              void* d_out, int out_size)
{
    const float* features = (const float*)d_in[0];
    const float* weight   = (const float*)d_in[1];
    const float* bias     = (const float*)d_in[2];
    const int*   nbr_idx  = (const int*)d_in[3];
    const int*   nbr_mask = (const int*)d_in[4];
    float*       out      = (float*)d_out;

    const int n_sites = in_sizes[0] / C;

    zero_kernel<<<1, 32>>>();

    const int cblocks = (n_sites + CB_SITES - 1) / CB_SITES;
    compact_kernel<<<cblocks, CB_THREADS>>>(nbr_idx, nbr_mask, n_sites);

    center_gemm_kernel<<<CG_BLOCKS, CG_THREADS>>>(features, weight, bias, out, n_sites);

    dim3 tgrid(PB_BLOCKS_X, KTAPS - 1);
    taps_kernel<<<tgrid, PB_THREADS>>>(features, weight, out);
}

// round 7
// speedup vs baseline: 1.9020x; 1.3044x over previous
#include <cuda_runtime.h>
#include <cstdint>

// Submanifold sparse conv — compacted per-offset gather-GEMM, pipelined pairs.
//  zero_kernel    : reset per-k counters
//  compact_kernel : per-k lists of (site, neighbor) for active off-center taps
//  center_gemm    : out = bias + F @ W[13]
//  taps_kernel    : out[site] += F[nb] @ W[k], W[k] in registers; warps own
//                   contiguous chunks, process entry PAIRS, 2-deep pipeline.
//
// features [N,32] f32, weight [27,32,32] f32 (k,ci,cout), bias [32] f32,
// nbr_idx [N,27] i32, nbr_mask [N,27] i32, out [N,32] f32.

#define C 32
#define KTAPS 27
#define KCENTER 13
#define NCAP 131072                     // per-k list capacity (even, 16B-aligned)

__device__ int  g_count[KTAPS];
__device__ int2 g_list[KTAPS * NCAP];   // (site, neighbor)

// ---------------------------------------------------------------- zero
__global__ void zero_kernel()
{
    if (threadIdx.x < KTAPS) g_count[threadIdx.x] = 0;
}

// ---------------------------------------------------------------- compact
#define CB_THREADS 256
#define CB_SPT 4
#define CB_SITES (CB_THREADS * CB_SPT)

__global__ void __launch_bounds__(CB_THREADS)
compact_kernel(const int* __restrict__ nbr_idx,
               const int* __restrict__ nbr_mask,
               int n_sites)
{
    __shared__ int scount[KTAPS];
    __shared__ int sbase[KTAPS];

    const int tid = threadIdx.x;
    if (tid < KTAPS) scount[tid] = 0;
    __syncthreads();

    const int base_site = blockIdx.x * CB_SITES;
    unsigned bits[CB_SPT];

    #pragma unroll
    for (int s = 0; s < CB_SPT; ++s) {
        const int site = base_site + s * CB_THREADS + tid;
        unsigned b = 0;
        if (site < n_sites) {
            const int* m = nbr_mask + site * KTAPS;
            #pragma unroll
            for (int k = 0; k < KTAPS; ++k)
                if (k != KCENTER && m[k]) b |= (1u << k);
        }
        bits[s] = b;
        unsigned t = b;
        while (t) {
            const int k = __ffs(t) - 1;
            t &= t - 1;
            atomicAdd(&scount[k], 1);
        }
    }
    __syncthreads();

    if (tid < KTAPS) {
        const int c = scount[tid];
        sbase[tid]  = c ? atomicAdd(&g_count[tid], c) : 0;
        scount[tid] = 0;
    }
    __syncthreads();

    #pragma unroll
    for (int s = 0; s < CB_SPT; ++s) {
        const int site = base_site + s * CB_THREADS + tid;
        unsigned t = bits[s];
        while (t) {
            const int k = __ffs(t) - 1;
            t &= t - 1;
            const int pos = sbase[k] + atomicAdd(&scount[k], 1);
            g_list[k * NCAP + pos] = make_int2(site, nbr_idx[site * KTAPS + k]);
        }
    }
}

// ---------------------------------------------------------------- center
#define CG_WARPS 16
#define CG_THREADS 512
#define CG_BLOCKS 296

__global__ void __launch_bounds__(CG_THREADS, 2)
center_gemm_kernel(const float* __restrict__ features,
                   const float* __restrict__ weight,
                   const float* __restrict__ bias,
                   float* __restrict__ out,
                   int n_sites)
{
    __shared__ float sf[CG_WARPS][C];

    const int tid  = threadIdx.x;
    const int lane = tid & 31;
    const int wib  = tid >> 5;

    float w[C];
    const float* w13 = weight + KCENTER * C * C;
    #pragma unroll
    for (int ci = 0; ci < C; ++ci)
        w[ci] = w13[ci * C + lane];

    const float my_bias = bias[lane];
    float* row = sf[wib];

    const int gwarp  = blockIdx.x * CG_WARPS + wib;
    const int nwarps = gridDim.x * CG_WARPS;

    float fvA = 0.f;
    if (gwarp < n_sites) fvA = features[gwarp * C + lane];

    for (int site = gwarp; site < n_sites; site += nwarps) {
        const int nsite = site + nwarps;
        float fvB = 0.f;
        if (nsite < n_sites) fvB = features[nsite * C + lane];

        row[lane] = fvA;
        __syncwarp();

        float a0 = my_bias, a1 = 0.f, a2 = 0.f, a3 = 0.f;
        #pragma unroll
        for (int g = 0; g < 8; ++g) {
            const float4 f = *reinterpret_cast<const float4*>(row + (g << 2));
            a0 += f.x * w[(g << 2) + 0];
            a1 += f.y * w[(g << 2) + 1];
            a2 += f.z * w[(g << 2) + 2];
            a3 += f.w * w[(g << 2) + 3];
        }
        __syncwarp();

        out[site * C + lane] = (a0 + a1) + (a2 + a3);
        fvA = fvB;
    }
}

// ---------------------------------------------------------------- taps
#define PB_WARPS 8
#define PB_THREADS 256
#define PB_BLOCKS_X 40

__global__ void __launch_bounds__(PB_THREADS)
taps_kernel(const float* __restrict__ features,
            const float* __restrict__ weight,
            float* __restrict__ out)
{
    // 4 staging rows per warp (double-buffered pairs)
    __shared__ float rows[PB_WARPS][4][C];

    int k = blockIdx.y;
    if (k >= KCENTER) ++k;

    const int tid  = threadIdx.x;
    const int lane = tid & 31;
    const int wib  = tid >> 5;

    // W[k][ci][lane] in registers
    float w[C];
    const float* wkp = weight + k * C * C;
    #pragma unroll
    for (int ci = 0; ci < C; ++ci)
        w[ci] = wkp[ci * C + lane];

    const int cnt = g_count[k];
    const int npairs = (cnt + 1) >> 1;
    const int warps_per_k = gridDim.x * PB_WARPS;
    const int wid_in_k = blockIdx.x * PB_WARPS + wib;
    const int chunk = (npairs + warps_per_k - 1) / warps_per_k;
    int p  = wid_in_k * chunk;
    const int pend = min(p + chunk, npairs);
    if (p >= pend) return;

    const int4* list2 = reinterpret_cast<const int4*>(g_list + k * NCAP);
    float (*myrows)[C] = rows[wib];

    // ---- pipeline prime ----
    // pairA: entry + features resident before loop body computes on it.
    int4 pairA = list2[p];                                    // uniform load
    int4 pairB = (p + 1 < pend) ? list2[p + 1] : pairA;
    float fvA0 = features[pairA.y * C + lane];
    float fvA1 = (2 * p + 1 < cnt) ? features[pairA.w * C + lane] : 0.f;

    for (;;) {
        // stage: entry 2 ahead, features 1 ahead (indep of this iter's compute)
        const bool hasB = (p + 1 < pend);
        int4 pairC = (p + 2 < pend) ? list2[p + 2] : pairA;
        float fvB0 = 0.f, fvB1 = 0.f;
        if (hasB) {
            fvB0 = features[pairB.y * C + lane];
            if (2 * (p + 1) + 1 < cnt) fvB1 = features[pairB.w * C + lane];
        }

        // compute pair A
        const int buf = (p & 1) << 1;
        float* r0 = myrows[buf + 0];
        float* r1 = myrows[buf + 1];
        r0[lane] = fvA0;
        r1[lane] = fvA1;
        __syncwarp();

        float a0 = 0.f, a1 = 0.f, a2 = 0.f, a3 = 0.f;
        float b0 = 0.f, b1 = 0.f, b2 = 0.f, b3 = 0.f;
        #pragma unroll
        for (int g = 0; g < 8; ++g) {
            const float4 f0 = *reinterpret_cast<const float4*>(r0 + (g << 2));
            const float4 f1 = *reinterpret_cast<const float4*>(r1 + (g << 2));
            a0 += f0.x * w[(g << 2) + 0];
            a1 += f0.y * w[(g << 2) + 1];
            a2 += f0.z * w[(g << 2) + 2];
            a3 += f0.w * w[(g << 2) + 3];
            b0 += f1.x * w[(g << 2) + 0];
            b1 += f1.y * w[(g << 2) + 1];
            b2 += f1.z * w[(g << 2) + 2];
            b3 += f1.w * w[(g << 2) + 3];
        }

        atomicAdd(&out[pairA.x * C + lane], (a0 + a1) + (a2 + a3));
        if (2 * p + 1 < cnt)
            atomicAdd(&out[pairA.z * C + lane], (b0 + b1) + (b2 + b3));

        if (!hasB) break;
        ++p;
        pairA = pairB; pairB = pairC;
        fvA0  = fvB0;  fvA1  = fvB1;
    }
}

// ---------------------------------------------------------------- launch
extern "C" void kernel_launch(void* const* d_in, const int* in_sizes, int n_in,
                              void* d_out, int out_size)
{
    const float* features = (const float*)d_in[0];
    const float* weight   = (const float*)d_in[1];
    const float* bias     = (const float*)d_in[2];
    const int*   nbr_idx  = (const int*)d_in[3];
    const int*   nbr_mask = (const int*)d_in[4];
    float*       out      = (float*)d_out;

    const int n_sites = in_sizes[0] / C;

    zero_kernel<<<1, 32>>>();

    const int cblocks = (n_sites + CB_SITES - 1) / CB_SITES;
    compact_kernel<<<cblocks, CB_THREADS>>>(nbr_idx, nbr_mask, n_sites);

    center_gemm_kernel<<<CG_BLOCKS, CG_THREADS>>>(features, weight, bias, out, n_sites);

    dim3 tgrid(PB_BLOCKS_X, KTAPS - 1);
    taps_kernel<<<tgrid, PB_THREADS>>>(features, weight, out);
}

// round 8
// speedup vs baseline: 1.9827x; 1.0424x over previous
#include <cuda_runtime.h>
#include <cstdint>

// Submanifold sparse conv — compacted per-offset gather-GEMM, pipelined pairs.
//  zero_kernel    : reset per-k counters
//  compact_kernel : element-parallel (coalesced) build of per-k (site,nb) lists
//  center_gemm    : out = bias + F @ W[13]
//  taps_kernel    : out[site] += F[nb] @ W[k], W[k] in registers; single-wave
//                   grid, contiguous chunks, entry PAIRS, 2-deep pipeline.

#define C 32
#define KTAPS 27
#define KCENTER 13
#define NCAP 131072

__device__ int  g_count[KTAPS];
__device__ int2 g_list[KTAPS * NCAP];

// ---------------------------------------------------------------- zero
__global__ void zero_kernel()
{
    if (threadIdx.x < KTAPS) g_count[threadIdx.x] = 0;
}

// ---------------------------------------------------------------- compact
// Element-parallel over the flat [n_sites*27] mask array. Coalesced reads.
#define CB_THREADS 256
#define CB_EPT 8                              // elements per thread
#define CB_ELEMS (CB_THREADS * CB_EPT)        // 2048 elements per block

__global__ void __launch_bounds__(CB_THREADS)
compact_kernel(const int* __restrict__ nbr_idx,
               const int* __restrict__ nbr_mask,
               int n_elems)
{
    __shared__ int scount[KTAPS];
    __shared__ int sbase[KTAPS];

    const int tid = threadIdx.x;
    if (tid < KTAPS) scount[tid] = 0;
    __syncthreads();

    const int base = blockIdx.x * CB_ELEMS;
    bool act[CB_EPT];

    // pass 1: coalesced mask read, per-block counts
    #pragma unroll
    for (int s = 0; s < CB_EPT; ++s) {
        const int e = base + s * CB_THREADS + tid;
        bool a = false;
        if (e < n_elems) {
            const int k = e % KTAPS;
            a = (k != KCENTER) && (nbr_mask[e] != 0);
            if (a) atomicAdd(&scount[k], 1);
        }
        act[s] = a;
    }
    __syncthreads();

    // reserve global space: one global atomic per k per block
    if (tid < KTAPS) {
        const int c = scount[tid];
        sbase[tid]  = c ? atomicAdd(&g_count[tid], c) : 0;
        scount[tid] = 0;                        // reuse as cursor
    }
    __syncthreads();

    // pass 2: write entries (idx read only for active elements)
    #pragma unroll
    for (int s = 0; s < CB_EPT; ++s) {
        if (act[s]) {
            const int e    = base + s * CB_THREADS + tid;
            const int site = e / KTAPS;
            const int k    = e - site * KTAPS;
            const int pos  = sbase[k] + atomicAdd(&scount[k], 1);
            g_list[k * NCAP + pos] = make_int2(site, nbr_idx[e]);
        }
    }
}

// ---------------------------------------------------------------- center
#define CG_WARPS 16
#define CG_THREADS 512
#define CG_BLOCKS 296

__global__ void __launch_bounds__(CG_THREADS, 2)
center_gemm_kernel(const float* __restrict__ features,
                   const float* __restrict__ weight,
                   const float* __restrict__ bias,
                   float* __restrict__ out,
                   int n_sites)
{
    __shared__ float sf[CG_WARPS][C];

    const int tid  = threadIdx.x;
    const int lane = tid & 31;
    const int wib  = tid >> 5;

    float w[C];
    const float* w13 = weight + KCENTER * C * C;
    #pragma unroll
    for (int ci = 0; ci < C; ++ci)
        w[ci] = w13[ci * C + lane];

    const float my_bias = bias[lane];
    float* row = sf[wib];

    const int gwarp  = blockIdx.x * CG_WARPS + wib;
    const int nwarps = gridDim.x * CG_WARPS;

    float fvA = 0.f;
    if (gwarp < n_sites) fvA = features[gwarp * C + lane];

    for (int site = gwarp; site < n_sites; site += nwarps) {
        const int nsite = site + nwarps;
        float fvB = 0.f;
        if (nsite < n_sites) fvB = features[nsite * C + lane];

        row[lane] = fvA;
        __syncwarp();

        float a0 = my_bias, a1 = 0.f, a2 = 0.f, a3 = 0.f;
        #pragma unroll
        for (int g = 0; g < 8; ++g) {
            const float4 f = *reinterpret_cast<const float4*>(row + (g << 2));
            a0 += f.x * w[(g << 2) + 0];
            a1 += f.y * w[(g << 2) + 1];
            a2 += f.z * w[(g << 2) + 2];
            a3 += f.w * w[(g << 2) + 3];
        }
        __syncwarp();

        out[site * C + lane] = (a0 + a1) + (a2 + a3);
        fvA = fvB;
    }
}

// ---------------------------------------------------------------- taps
#define PB_WARPS 8
#define PB_THREADS 256
#define PB_BLOCKS_X 17      // 26*17 = 442 blocks ~= one wave at 3 blocks/SM

__global__ void __launch_bounds__(PB_THREADS)
taps_kernel(const float* __restrict__ features,
            const float* __restrict__ weight,
            float* __restrict__ out)
{
    __shared__ float rows[PB_WARPS][4][C];

    int k = blockIdx.y;
    if (k >= KCENTER) ++k;

    const int tid  = threadIdx.x;
    const int lane = tid & 31;
    const int wib  = tid >> 5;

    float w[C];
    const float* wkp = weight + k * C * C;
    #pragma unroll
    for (int ci = 0; ci < C; ++ci)
        w[ci] = wkp[ci * C + lane];

    const int cnt = g_count[k];
    const int npairs = (cnt + 1) >> 1;
    const int warps_per_k = gridDim.x * PB_WARPS;
    const int wid_in_k = blockIdx.x * PB_WARPS + wib;
    const int chunk = (npairs + warps_per_k - 1) / warps_per_k;
    int p  = wid_in_k * chunk;
    const int pend = min(p + chunk, npairs);
    if (p >= pend) return;

    const int4* list2 = reinterpret_cast<const int4*>(g_list + k * NCAP);
    float (*myrows)[C] = rows[wib];

    int4 pairA = list2[p];
    int4 pairB = (p + 1 < pend) ? list2[p + 1] : pairA;
    float fvA0 = features[pairA.y * C + lane];
    float fvA1 = (2 * p + 1 < cnt) ? features[pairA.w * C + lane] : 0.f;

    for (;;) {
        const bool hasB = (p + 1 < pend);
        int4 pairC = (p + 2 < pend) ? list2[p + 2] : pairA;
        float fvB0 = 0.f, fvB1 = 0.f;
        if (hasB) {
            fvB0 = features[pairB.y * C + lane];
            if (2 * (p + 1) + 1 < cnt) fvB1 = features[pairB.w * C + lane];
        }

        const int buf = (p & 1) << 1;
        float* r0 = myrows[buf + 0];
        float* r1 = myrows[buf + 1];
        r0[lane] = fvA0;
        r1[lane] = fvA1;
        __syncwarp();

        float a0 = 0.f, a1 = 0.f, a2 = 0.f, a3 = 0.f;
        float b0 = 0.f, b1 = 0.f, b2 = 0.f, b3 = 0.f;
        #pragma unroll
        for (int g = 0; g < 8; ++g) {
            const float4 f0 = *reinterpret_cast<const float4*>(r0 + (g << 2));
            const float4 f1 = *reinterpret_cast<const float4*>(r1 + (g << 2));
            a0 += f0.x * w[(g << 2) + 0];
            a1 += f0.y * w[(g << 2) + 1];
            a2 += f0.z * w[(g << 2) + 2];
            a3 += f0.w * w[(g << 2) + 3];
            b0 += f1.x * w[(g << 2) + 0];
            b1 += f1.y * w[(g << 2) + 1];
            b2 += f1.z * w[(g << 2) + 2];
            b3 += f1.w * w[(g << 2) + 3];
        }

        atomicAdd(&out[pairA.x * C + lane], (a0 + a1) + (a2 + a3));
        if (2 * p + 1 < cnt)
            atomicAdd(&out[pairA.z * C + lane], (b0 + b1) + (b2 + b3));

        if (!hasB) break;
        ++p;
        pairA = pairB; pairB = pairC;
        fvA0  = fvB0;  fvA1  = fvB1;
    }
}

// ---------------------------------------------------------------- launch
extern "C" void kernel_launch(void* const* d_in, const int* in_sizes, int n_in,
                              void* d_out, int out_size)
{
    const float* features = (const float*)d_in[0];
    const float* weight   = (const float*)d_in[1];
    const float* bias     = (const float*)d_in[2];
    const int*   nbr_idx  = (const int*)d_in[3];
    const int*   nbr_mask = (const int*)d_in[4];
    float*       out      = (float*)d_out;

    const int n_sites = in_sizes[0] / C;
    const int n_elems = n_sites * KTAPS;

    zero_kernel<<<1, 32>>>();

    const int cblocks = (n_elems + CB_ELEMS - 1) / CB_ELEMS;
    compact_kernel<<<cblocks, CB_THREADS>>>(nbr_idx, nbr_mask, n_elems);

    center_gemm_kernel<<<CG_BLOCKS, CG_THREADS>>>(features, weight, bias, out, n_sites);

    dim3 tgrid(PB_BLOCKS_X, KTAPS - 1);
    taps_kernel<<<tgrid, PB_THREADS>>>(features, weight, out);
}